// round 16
// baseline (speedup 1.0000x reference)
#include <cuda_runtime.h>
#include <stdint.h>

// Problem constants
#define B 8
#define H 12
#define L 1024
#define D 768
#define KSEL 512
#define HL (H * L)                       // 12288 rows per batch
#define SPLITS 96
#define ROWS_PER_SPLIT (HL / SPLITS)     // 128
#define L4 (L / 4)                       // 256 float4 per score row
#define D4 (D / 4)                       // 192 float4 per token row

// Scratch (device globals). Zero at load; kernel restores zeros every call
// -> graph-replay safe.
__device__ float g_imp[B * L];
__device__ int   g_selidx[B * KSEL];
__device__ int   g_count[B];
__device__ int   g_flag[B];
__device__ int   g_done[B];

// ---------------------------------------------------------------------------
// Single fused kernel, grid (B, SPLITS), block 256.
// __launch_bounds__(256, 6): 148 SMs x 6 = 888 >= 768 blocks -> the whole
// grid is co-resident, so the flag spin-wait is deadlock-free.
//   0) L2 prefetch of this block's 32KB slice of hidden_states (scores are
//      streamed with __ldcs/evict-first, so hidden survives in L2)
//   1) colsum: stream 128 rows (float4, unroll 16), f32 atomics into g_imp
//   2) last-arriving block per batch: radix top-K select + compact,
//      EARLY flag release, then mask write + scratch reset
//   3) all blocks: spin on flag[b], then warp-per-row gather (6 independent
//      float4 loads per lane, streaming stores) -- reads are L2 hits.
// ---------------------------------------------------------------------------
__global__ void __launch_bounds__(256, 6) router_fused_kernel(
    const float4* __restrict__ scores4, const float* __restrict__ amask,
    const float* __restrict__ hidden,
    float* __restrict__ imp, int* __restrict__ selidx,
    int* __restrict__ count, int* __restrict__ flag, int* __restrict__ done,
    float* __restrict__ out)
{
    const int b = blockIdx.x;
    const int s = blockIdx.y;
    const int t = threadIdx.x;
    const int lane = t & 31;
    const int wid  = t >> 5;

    // ---- 0) L2 prefetch of hidden (one 128B line per thread; 768 blocks
    //         cover the 25.2MB array exactly) ----
    {
        const char* hb = (const char*)hidden
            + (((size_t)(b * SPLITS + s)) << 15) + ((size_t)t << 7);
        asm volatile("prefetch.global.L2 [%0];" :: "l"(hb));
    }

    // ---- 1) colsum phase ----
    {
        const float4* base =
            scores4 + ((size_t)b * HL + (size_t)s * ROWS_PER_SPLIT) * L4 + t;
        float4 acc = make_float4(0.f, 0.f, 0.f, 0.f);
#pragma unroll 16
        for (int r = 0; r < ROWS_PER_SPLIT; ++r) {
            const float4 x = __ldcs(base + (size_t)r * L4);
            acc.x += x.x; acc.y += x.y; acc.z += x.z; acc.w += x.w;
        }
        float* dst = imp + b * L + 4 * t;
        atomicAdd(dst + 0, acc.x);
        atomicAdd(dst + 1, acc.y);
        atomicAdd(dst + 2, acc.z);
        atomicAdd(dst + 3, acc.w);
    }

    // ---- arrival ----
    __threadfence();
    __syncthreads();
    __shared__ int s_ticket;
    if (t == 0) s_ticket = atomicAdd(&count[b], 1);
    __syncthreads();

    // ---- 2) select on the last-arriving block ----
    if (s_ticket == SPLITS - 1) {
        __threadfence();               // acquire: all batch-b atomics visible

        const float4 iv = *((const float4*)(imp + b * L) + t);

        unsigned k[4];
        {
            const float f[4] = {iv.x, iv.y, iv.z, iv.w};
#pragma unroll
            for (int i = 0; i < 4; ++i) {
                const unsigned ub = __float_as_uint(f[i]);
                k[i] = ub ^ ((ub & 0x80000000u) ? 0xFFFFFFFFu : 0x80000000u);
            }
        }

        __shared__ int      hist[256];
        __shared__ unsigned s_pref;
        __shared__ int      s_k;
        __shared__ int      wtot[8];

        if (t == 0) { s_pref = 0u; s_k = KSEL; }
        __syncthreads();

        // 4-pass byte radix select: 512th-largest key + tie quota
#pragma unroll
        for (int pass = 0; pass < 4; ++pass) {
            const int shift = 24 - 8 * pass;
            const unsigned pref = s_pref;
            const int kcur = s_k;

            hist[t] = 0;
            __syncthreads();
#pragma unroll
            for (int i = 0; i < 4; ++i) {
                const bool active = (pass == 0) ||
                    (((k[i] ^ pref) >> (shift + 8)) == 0u);
                if (active) atomicAdd(&hist[(k[i] >> shift) & 0xFF], 1);
            }
            __syncthreads();

            const int h = hist[t];
            int v = h;
#pragma unroll
            for (int d = 1; d < 32; d <<= 1) {
                const int n = __shfl_down_sync(0xffffffffu, v, d);
                if (lane + d < 32) v += n;
            }
            const int wsum = __shfl_sync(0xffffffffu, v, 0);
            if (lane == 0) wtot[wid] = wsum;
            __syncthreads();
            int above = 0;
#pragma unroll
            for (int w = 0; w < 8; ++w) if (w > wid) above += wtot[w];
            const int ge = v + above;        // active keys with bin >= t
            const int gt = ge - h;
            if (gt < kcur && ge >= kcur) {   // exactly one bin fires
                s_pref = pref | ((unsigned)t << shift);
                s_k    = kcur - gt;
            }
            __syncthreads();
        }

        const unsigned T  = s_pref;
        const int      kq = s_k;      // tie slots (>= 1), lowest indices win

        // tie ranking (ascending index) via block scan
        bool tie[4];
        int tiecnt = 0;
#pragma unroll
        for (int i = 0; i < 4; ++i) { tie[i] = (k[i] == T); tiecnt += tie[i]; }

        int incl = tiecnt;
#pragma unroll
        for (int d = 1; d < 32; d <<= 1) {
            const int n = __shfl_up_sync(0xffffffffu, incl, d);
            if (lane >= d) incl += n;
        }
        if (lane == 31) wtot[wid] = incl;
        __syncthreads();
        int base = 0;
#pragma unroll
        for (int w = 0; w < 8; ++w) if (w < wid) base += wtot[w];
        int trank = base + incl - tiecnt;

        bool sel[4];
        int selcnt = 0;
#pragma unroll
        for (int i = 0; i < 4; ++i) {
            bool sl = (k[i] > T);
            if (tie[i]) { sl = (trank < kq); ++trank; }
            sel[i] = sl; selcnt += sl;
        }
        __syncthreads();

        // compaction scan (ascending index)
        int sincl = selcnt;
#pragma unroll
        for (int d = 1; d < 32; d <<= 1) {
            const int n = __shfl_up_sync(0xffffffffu, sincl, d);
            if (lane >= d) sincl += n;
        }
        if (lane == 31) wtot[wid] = sincl;
        __syncthreads();
        int sbase = 0;
#pragma unroll
        for (int w = 0; w < 8; ++w) if (w < wid) sbase += wtot[w];
        int pos = sbase + sincl - selcnt;

#pragma unroll
        for (int i = 0; i < 4; ++i) {
            if (sel[i]) { selidx[b * KSEL + pos] = 4 * t + i; ++pos; }
        }

        // EARLY release: selidx complete -> wake this batch's gatherers
        __threadfence();
        __syncthreads();
        if (t == 0) atomicExch(&flag[b], 1);

        // mask write + scratch reset off the wait path
        float* mout = out + (size_t)B * (KSEL + 1) * D
                          + (size_t)b * (KSEL + 1);
        for (int r = t; r <= KSEL; r += 256) {
            if (r == 0) mout[0] = 0.f;
            else        mout[r] = amask[(size_t)b * L
                                        + selidx[b * KSEL + r - 1]];
        }
        *((float4*)(imp + b * L) + t) = make_float4(0.f, 0.f, 0.f, 0.f);
        if (t == 0) count[b] = 0;
    }

    // ---- 3) gather phase: wait for own batch's selidx ----
    if (t == 0) {
        while (((volatile int*)flag)[b] == 0) __nanosleep(32);
    }
    __syncthreads();
    __threadfence();   // acquire selidx

    // warp w copies row r = s + 96*w (w < nrows; 6 rows for s<=32, else 5)
    const int nrows = (s <= KSEL - 5 * SPLITS) ? 6 : 5;
    if (wid < nrows) {
        const int r = s + SPLITS * wid;
        int j = 0;
        if (lane == 0 && r != 0) j = selidx[b * KSEL + r - 1];
        j = __shfl_sync(0xffffffffu, j, 0);

        const float4* src = (const float4*)(hidden
            + ((size_t)b * L + j) * D) + lane;
        float4* dst = (float4*)(out
            + ((size_t)b * (KSEL + 1) + r) * D) + lane;

        float4 v[6];
#pragma unroll
        for (int q = 0; q < 6; ++q) v[q] = src[32 * q];
#pragma unroll
        for (int q = 0; q < 6; ++q) __stcs(dst + 32 * q, v[q]);
    }

    // ---- completion: last gatherer of each batch resets flags ----
    __syncthreads();
    if (t == 0) {
        if (atomicAdd(&done[b], 1) == SPLITS - 1) {
            done[b] = 0;
            flag[b] = 0;
        }
    }
}

// ---------------------------------------------------------------------------
extern "C" void kernel_launch(void* const* d_in, const int* in_sizes, int n_in,
                              void* d_out, int out_size)
{
    const float* hidden = (const float*)d_in[0];   // [B, L, D]
    const float* amask  = (const float*)d_in[1];   // [B, 1, 1, L]
    const float* scores = (const float*)d_in[2];   // [B, H, L, L]
    float* out = (float*)d_out;                    // tokens then mask, f32

    float* d_imp;
    int *d_selidx, *d_count, *d_flag, *d_done;
    cudaGetSymbolAddress((void**)&d_imp,    g_imp);
    cudaGetSymbolAddress((void**)&d_selidx, g_selidx);
    cudaGetSymbolAddress((void**)&d_count,  g_count);
    cudaGetSymbolAddress((void**)&d_flag,   g_flag);
    cudaGetSymbolAddress((void**)&d_done,   g_done);

    dim3 grid(B, SPLITS);
    router_fused_kernel<<<grid, 256>>>(
        (const float4*)scores, amask, hidden,
        d_imp, d_selidx, d_count, d_flag, d_done, out);
}

// round 17
// speedup vs baseline: 1.0093x; 1.0093x over previous
#include <cuda_runtime.h>
#include <stdint.h>

// Problem constants
#define B 8
#define H 12
#define L 1024
#define D 768
#define KSEL 512
#define HL (H * L)                       // 12288 rows per batch
#define SPLITS 96
#define ROWS_PER_SPLIT (HL / SPLITS)     // 128
#define L4 (L / 4)                       // 256 float4 per score row
#define D4 (D / 4)                       // 192 float4 per token row
#define NCOL (B * SPLITS)                // 768 colsum blocks
#define GPB 65                           // gather blocks per batch (8 rows each)
#define NGATH (B * GPB)                  // 520 gather blocks
#define NBLK (NCOL + NGATH)              // 1288 total

// Scratch (device globals). Zero at load; kernel restores zeros every call
// -> graph-replay safe.
__device__ float g_imp[B * L];
__device__ int   g_selidx[B * KSEL];
__device__ int   g_count[B];
__device__ int   g_flag[B];
__device__ int   g_done[B];

// ---------------------------------------------------------------------------
// Heterogeneous single grid, 1288 blocks of 256 threads.
//   blocks [0, 768):   colsum (stream 128 rows, f32 atomic flush) + L2
//                      prefetch of hidden; per-batch last arrival runs the
//                      radix top-K select + compact, releases flag[b] early,
//                      then writes the mask and resets scratch. Pure: exits
//                      right after -- the streaming phase carries no gather
//                      baggage.
//   blocks [768,1288): dedicated gather blocks. They park on flag[b]
//                      (~120 are co-resident with colsum; the rest flow in
//                      as colsum blocks retire -- dispatch is in increasing
//                      block-index order, and wave-1 capacity ~888 >= 768,
//                      so every flag is set by an already-running block:
//                      deadlock-free). Each copies 8 token rows, one warp
//                      per row, 6 independent float4 loads (L2 hits via the
//                      prefetch), streaming stores.
// ---------------------------------------------------------------------------
__global__ void __launch_bounds__(256) router_hetero_kernel(
    const float4* __restrict__ scores4, const float* __restrict__ amask,
    const float* __restrict__ hidden,
    float* __restrict__ imp, int* __restrict__ selidx,
    int* __restrict__ count, int* __restrict__ flag, int* __restrict__ done,
    float* __restrict__ out)
{
    const int i = blockIdx.x;
    const int t = threadIdx.x;
    const int lane = t & 31;
    const int wid  = t >> 5;

    if (i < NCOL) {
        // =================== colsum / select block ===================
        const int b = i / SPLITS;
        const int s = i - b * SPLITS;

        // L2 prefetch of hidden (one 128B line per thread; the 768 colsum
        // blocks cover the 25.2MB array exactly)
        {
            const char* hb = (const char*)hidden
                + (((size_t)i) << 15) + ((size_t)t << 7);
            asm volatile("prefetch.global.L2 [%0];" :: "l"(hb));
        }

        // colsum: stream 128 rows, accumulate 1 float4 per thread
        {
            const float4* base = scores4
                + ((size_t)b * HL + (size_t)s * ROWS_PER_SPLIT) * L4 + t;
            float4 acc = make_float4(0.f, 0.f, 0.f, 0.f);
#pragma unroll 16
            for (int r = 0; r < ROWS_PER_SPLIT; ++r) {
                const float4 x = __ldcs(base + (size_t)r * L4);
                acc.x += x.x; acc.y += x.y; acc.z += x.z; acc.w += x.w;
            }
            float* dst = imp + b * L + 4 * t;
            atomicAdd(dst + 0, acc.x);
            atomicAdd(dst + 1, acc.y);
            atomicAdd(dst + 2, acc.z);
            atomicAdd(dst + 3, acc.w);
        }

        // arrival: last block per batch runs the selection
        __threadfence();
        __syncthreads();
        __shared__ int s_ticket;
        if (t == 0) s_ticket = atomicAdd(&count[b], 1);
        __syncthreads();
        if (s_ticket != SPLITS - 1) return;
        __threadfence();           // acquire: all batch-b atomics visible

        const float4 iv = *((const float4*)(imp + b * L) + t);

        unsigned k[4];
        {
            const float f[4] = {iv.x, iv.y, iv.z, iv.w};
#pragma unroll
            for (int q = 0; q < 4; ++q) {
                const unsigned ub = __float_as_uint(f[q]);
                k[q] = ub ^ ((ub & 0x80000000u) ? 0xFFFFFFFFu : 0x80000000u);
            }
        }

        __shared__ int      hist[256];
        __shared__ unsigned s_pref;
        __shared__ int      s_k;
        __shared__ int      wtot[8];

        if (t == 0) { s_pref = 0u; s_k = KSEL; }
        __syncthreads();

        // 4-pass byte radix select: 512th-largest key + tie quota
#pragma unroll
        for (int pass = 0; pass < 4; ++pass) {
            const int shift = 24 - 8 * pass;
            const unsigned pref = s_pref;
            const int kcur = s_k;

            hist[t] = 0;
            __syncthreads();
#pragma unroll
            for (int q = 0; q < 4; ++q) {
                const bool active = (pass == 0) ||
                    (((k[q] ^ pref) >> (shift + 8)) == 0u);
                if (active) atomicAdd(&hist[(k[q] >> shift) & 0xFF], 1);
            }
            __syncthreads();

            const int h = hist[t];
            int v = h;
#pragma unroll
            for (int d = 1; d < 32; d <<= 1) {
                const int n = __shfl_down_sync(0xffffffffu, v, d);
                if (lane + d < 32) v += n;
            }
            const int wsum = __shfl_sync(0xffffffffu, v, 0);
            if (lane == 0) wtot[wid] = wsum;
            __syncthreads();
            int above = 0;
#pragma unroll
            for (int w = 0; w < 8; ++w) if (w > wid) above += wtot[w];
            const int ge = v + above;        // active keys with bin >= t
            const int gt = ge - h;
            if (gt < kcur && ge >= kcur) {   // exactly one bin fires
                s_pref = pref | ((unsigned)t << shift);
                s_k    = kcur - gt;
            }
            __syncthreads();
        }

        const unsigned T  = s_pref;
        const int      kq = s_k;     // tie slots (>= 1), lowest indices win

        // tie ranking (ascending index) via block scan
        bool tie[4];
        int tiecnt = 0;
#pragma unroll
        for (int q = 0; q < 4; ++q) { tie[q] = (k[q] == T); tiecnt += tie[q]; }

        int incl = tiecnt;
#pragma unroll
        for (int d = 1; d < 32; d <<= 1) {
            const int n = __shfl_up_sync(0xffffffffu, incl, d);
            if (lane >= d) incl += n;
        }
        if (lane == 31) wtot[wid] = incl;
        __syncthreads();
        int base = 0;
#pragma unroll
        for (int w = 0; w < 8; ++w) if (w < wid) base += wtot[w];
        int trank = base + incl - tiecnt;

        bool sel[4];
        int selcnt = 0;
#pragma unroll
        for (int q = 0; q < 4; ++q) {
            bool sl = (k[q] > T);
            if (tie[q]) { sl = (trank < kq); ++trank; }
            sel[q] = sl; selcnt += sl;
        }
        __syncthreads();

        // compaction scan (ascending index)
        int sincl = selcnt;
#pragma unroll
        for (int d = 1; d < 32; d <<= 1) {
            const int n = __shfl_up_sync(0xffffffffu, sincl, d);
            if (lane >= d) sincl += n;
        }
        if (lane == 31) wtot[wid] = sincl;
        __syncthreads();
        int sbase = 0;
#pragma unroll
        for (int w = 0; w < 8; ++w) if (w < wid) sbase += wtot[w];
        int pos = sbase + sincl - selcnt;

#pragma unroll
        for (int q = 0; q < 4; ++q) {
            if (sel[q]) { selidx[b * KSEL + pos] = 4 * t + q; ++pos; }
        }

        // EARLY release: selidx complete -> wake this batch's gatherers
        __threadfence();
        __syncthreads();
        if (t == 0) atomicExch(&flag[b], 1);

        // mask write + scratch reset off the wait path
        float* mout = out + (size_t)B * (KSEL + 1) * D
                          + (size_t)b * (KSEL + 1);
        for (int r = t; r <= KSEL; r += 256) {
            if (r == 0) mout[0] = 0.f;
            else        mout[r] = amask[(size_t)b * L
                                        + selidx[b * KSEL + r - 1]];
        }
        *((float4*)(imp + b * L) + t) = make_float4(0.f, 0.f, 0.f, 0.f);
        if (t == 0) count[b] = 0;
        return;
    }

    // ====================== dedicated gather block ======================
    {
        const int g = i - NCOL;          // 0..519
        const int b = g / GPB;
        const int c = g - b * GPB;       // 0..64 -> rows c*8 .. c*8+7

        // park until this batch's selidx is published
        if (t == 0) {
            while (((volatile int*)flag)[b] == 0) __nanosleep(64);
        }
        __syncthreads();
        __threadfence();   // acquire selidx

        const int r = c * 8 + wid;       // warp per row, 0..519
        if (r <= KSEL) {
            int j = 0;
            if (lane == 0 && r != 0) j = selidx[b * KSEL + r - 1];
            j = __shfl_sync(0xffffffffu, j, 0);

            const float4* src = (const float4*)(hidden
                + ((size_t)b * L + j) * D) + lane;
            float4* dst = (float4*)(out
                + ((size_t)b * (KSEL + 1) + r) * D) + lane;

            float4 v[6];
#pragma unroll
            for (int q = 0; q < 6; ++q) v[q] = src[32 * q];
#pragma unroll
            for (int q = 0; q < 6; ++q) __stcs(dst + 32 * q, v[q]);
        }

        // last finishing gather block of each batch resets the flags
        __syncthreads();
        if (t == 0) {
            if (atomicAdd(&done[b], 1) == GPB - 1) {
                done[b] = 0;
                flag[b] = 0;
            }
        }
    }
}

// ---------------------------------------------------------------------------
extern "C" void kernel_launch(void* const* d_in, const int* in_sizes, int n_in,
                              void* d_out, int out_size)
{
    const float* hidden = (const float*)d_in[0];   // [B, L, D]
    const float* amask  = (const float*)d_in[1];   // [B, 1, 1, L]
    const float* scores = (const float*)d_in[2];   // [B, H, L, L]
    float* out = (float*)d_out;                    // tokens then mask, f32

    float* d_imp;
    int *d_selidx, *d_count, *d_flag, *d_done;
    cudaGetSymbolAddress((void**)&d_imp,    g_imp);
    cudaGetSymbolAddress((void**)&d_selidx, g_selidx);
    cudaGetSymbolAddress((void**)&d_count,  g_count);
    cudaGetSymbolAddress((void**)&d_flag,   g_flag);
    cudaGetSymbolAddress((void**)&d_done,   g_done);

    router_hetero_kernel<<<NBLK, 256>>>(
        (const float4*)scores, amask, hidden,
        d_imp, d_selidx, d_count, d_flag, d_done, out);
}